// round 2
// baseline (speedup 1.0000x reference)
#include <cuda_runtime.h>
#include <cuda_bf16.h>
#include <math.h>

// ---------------------------------------------------------------------------
// Problem constants (fixed-shape registry problem)
//   N=50000 nodes, E=800000 edges, C_IN=128, C_H=64, 9 GCN layers
// ---------------------------------------------------------------------------
#define MAXN 50000
#define MAXE 800000
#define CH   64

// ---------------------------------------------------------------------------
// Scratch (device globals; no allocation allowed)
// ---------------------------------------------------------------------------
__device__ float g_H[MAXN * CH];        // current node features
__device__ float g_G[MAXN * CH];        // g = (h@W)*dinv  /  h@Wn at the end
__device__ int   g_cnt[MAXN];           // in-degree counts
__device__ int   g_rowptr[MAXN + 1];    // CSR row pointers (by dst)
__device__ int   g_cursor[MAXN];        // fill cursors
__device__ int   g_csr[MAXE];           // src ids sorted by dst
__device__ float g_dinv[MAXN];          // 1/sqrt(deg+1)
__device__ int   g_blocksum[256];       // scan partials
__device__ float g_pool[16 * CH];       // per-graph pooled features
__device__ float g_rterm[16];           // per-graph readout scalar

// ---------------------------------------------------------------------------
// Preprocessing: degree histogram + CSR build
// ---------------------------------------------------------------------------
__global__ void zero_kernel(int N) {
    int i = blockIdx.x * blockDim.x + threadIdx.x;
    if (i < N) g_cnt[i] = 0;
    if (i < 16 * CH) g_pool[i] = 0.f;
}

__global__ void count_kernel(const int* __restrict__ ei, int E) {
    int e = blockIdx.x * blockDim.x + threadIdx.x;
    if (e < E) atomicAdd(&g_cnt[ei[E + e]], 1);   // dst = ei[1][e]
}

__global__ void scan_partial(int N) {
    __shared__ int s[256];
    int t = threadIdx.x;
    int i = blockIdx.x * 256 + t;
    int v = (i < N) ? g_cnt[i] : 0;
    s[t] = v; __syncthreads();
    #pragma unroll
    for (int d = 1; d < 256; d <<= 1) {
        int x = (t >= d) ? s[t - d] : 0;
        __syncthreads();
        s[t] += x;
        __syncthreads();
    }
    if (i < N) g_rowptr[i] = s[t] - v;            // exclusive within block
    if (t == 255) g_blocksum[blockIdx.x] = s[255];
}

__global__ void scan_block(int nb) {
    __shared__ int s[256];
    int t = threadIdx.x;
    int v = (t < nb) ? g_blocksum[t] : 0;
    s[t] = v; __syncthreads();
    #pragma unroll
    for (int d = 1; d < 256; d <<= 1) {
        int x = (t >= d) ? s[t - d] : 0;
        __syncthreads();
        s[t] += x;
        __syncthreads();
    }
    if (t < nb) g_blocksum[t] = s[t] - v;         // exclusive
}

__global__ void finalize_meta(int N, int E) {
    int i = blockIdx.x * blockDim.x + threadIdx.x;
    if (i < N) {
        int rp = g_rowptr[i] + g_blocksum[i >> 8];
        g_rowptr[i] = rp;
        g_cursor[i] = rp;
        g_dinv[i]   = rsqrtf((float)g_cnt[i] + 1.0f);
        if (i == 0) g_rowptr[N] = E;
    }
}

__global__ void fill_csr(const int* __restrict__ ei, int E) {
    int e = blockIdx.x * blockDim.x + threadIdx.x;
    if (e < E) {
        int s = ei[e];
        int d = ei[E + e];
        int pos = atomicAdd(&g_cursor[d], 1);
        g_csr[pos] = s;
    }
}

// ---------------------------------------------------------------------------
// GEMM: Y[N,64] = (X[N,CIN] @ W[CIN,64]) * (dinv[r] if scale)  — fp32
// Block: 256 threads -> 128 rows x 64 cols, 8x4 register tile / thread
// ---------------------------------------------------------------------------
template <int CIN, bool SCALE>
__global__ void __launch_bounds__(256)
gemm64(const float* __restrict__ X, const float* __restrict__ W,
       float* __restrict__ Y, int N)
{
    __shared__ __align__(16) float hs[32][129];   // k-tile x row (padded)
    __shared__ __align__(16) float ws[32][64];    // k-tile x col
    const int tid = threadIdx.x;
    const int tx  = tid & 15;        // col group (4 cols)
    const int ty  = tid >> 4;        // row group (8 rows)
    const int row0 = blockIdx.x * 128;

    float acc[8][4];
    #pragma unroll
    for (int j = 0; j < 8; j++)
        #pragma unroll
        for (int q = 0; q < 4; q++) acc[j][q] = 0.f;

    for (int k0 = 0; k0 < CIN; k0 += 32) {
        // stage X tile (transposed into smem, coalesced gmem reads)
        #pragma unroll
        for (int i = 0; i < 16; i++) {
            int idx = tid + 256 * i;          // 0..4095
            int r = idx >> 5, kk = idx & 31;
            int gr = row0 + r;
            hs[kk][r] = (gr < N) ? X[gr * CIN + k0 + kk] : 0.f;
        }
        // stage W tile
        #pragma unroll
        for (int i = 0; i < 8; i++) {
            int idx = tid + 256 * i;          // 0..2047
            int k = idx >> 6, c = idx & 63;
            ws[k][c] = W[(k0 + k) * 64 + c];
        }
        __syncthreads();
        #pragma unroll
        for (int k = 0; k < 32; k++) {
            float4 wv = *(const float4*)&ws[k][tx * 4];
            #pragma unroll
            for (int j = 0; j < 8; j++) {
                float hv = hs[k][ty * 8 + j];
                acc[j][0] += hv * wv.x;
                acc[j][1] += hv * wv.y;
                acc[j][2] += hv * wv.z;
                acc[j][3] += hv * wv.w;
            }
        }
        __syncthreads();
    }
    #pragma unroll
    for (int j = 0; j < 8; j++) {
        int r = row0 + ty * 8 + j;
        if (r < N) {
            float s = SCALE ? g_dinv[r] : 1.0f;
            float4 o = make_float4(acc[j][0] * s, acc[j][1] * s,
                                   acc[j][2] * s, acc[j][3] * s);
            *(float4*)&Y[r * 64 + tx * 4] = o;
        }
    }
}

// ---------------------------------------------------------------------------
// Gather: H[v] = relu(dinv[v] * (G[v] + sum_{e: dst=v} G[src_e]) + bias)
// warp per node; lane owns a float2 (2 channels)
// ---------------------------------------------------------------------------
__global__ void gather_relu(const float* __restrict__ G,
                            const float* __restrict__ bias,
                            float* __restrict__ H, int N)
{
    int v = (blockIdx.x * blockDim.x + threadIdx.x) >> 5;
    int lane = threadIdx.x & 31;
    if (v >= N) return;

    int s = __ldg(&g_rowptr[v]), e = __ldg(&g_rowptr[v + 1]);
    float2 acc = *(const float2*)&G[v * 64 + lane * 2];  // self term

    for (int p = s; p < e; p += 32) {
        int m = min(32, e - p);
        int sl = (lane < m) ? __ldg(&g_csr[p + lane]) : 0;
        for (int j = 0; j < m; j++) {
            int src = __shfl_sync(0xffffffffu, sl, j);
            float2 gv = *(const float2*)&G[src * 64 + lane * 2];
            acc.x += gv.x; acc.y += gv.y;
        }
    }
    float dv = g_dinv[v];
    float2 b2 = *(const float2*)&bias[lane * 2];
    float hx = fmaxf(fmaf(dv, acc.x, b2.x), 0.f);
    float hy = fmaxf(fmaf(dv, acc.y, b2.y), 0.f);
    *(float2*)&H[v * 64 + lane * 2] = make_float2(hx, hy);
}

// ---------------------------------------------------------------------------
// Global add pool: per-block smem accumulator (16 graphs x 64 ch), one
// global atomic flush per block -> ~640 atomics/block instead of per-element.
// ---------------------------------------------------------------------------
__global__ void pool_kernel(const float* __restrict__ Hf, int N,
                            const int* __restrict__ np)
{
    __shared__ float sp[16 * CH];
    int n = *np;
    for (int i = threadIdx.x; i < 16 * CH; i += blockDim.x) sp[i] = 0.f;
    __syncthreads();

    long total = (long)N * 64;
    long stride = (long)gridDim.x * blockDim.x;
    int cur = -1; float accv = 0.f;
    for (long idx = blockIdx.x * (long)blockDim.x + threadIdx.x;
         idx < total; idx += stride) {
        int r = (int)(idx >> 6), c = (int)(idx & 63);
        int slot = (r / n) * 64 + c;
        if (slot != cur) {
            if (cur >= 0) atomicAdd(&sp[cur], accv);
            cur = slot; accv = 0.f;
        }
        accv += Hf[idx];
    }
    if (cur >= 0) atomicAdd(&sp[cur], accv);
    __syncthreads();
    for (int i = threadIdx.x; i < 16 * CH; i += blockDim.x)
        if (sp[i] != 0.f) atomicAdd(&g_pool[i], sp[i]);
}

// ---------------------------------------------------------------------------
// Per-graph readout scalar: rterm[b] = sum_c relu((pool@Wp)[b,c]) * Wa[64+c]
// ---------------------------------------------------------------------------
__global__ void graph_term(const float* __restrict__ Wp,
                           const float* __restrict__ Wa,
                           int N, const int* __restrict__ np)
{
    int n = *np; int nb = N / n; if (nb > 16) nb = 16;
    int tid = threadIdx.x;               // 1024 threads, 16 graphs x 64 ch
    int b = tid >> 6, c = tid & 63;
    float val = 0.f;
    if (b < nb) {
        float rep = 0.f;
        #pragma unroll 8
        for (int k = 0; k < 64; k++) rep += g_pool[b * 64 + k] * Wp[k * 64 + c];
        val = fmaxf(rep, 0.f) * Wa[64 + c];
    }
    #pragma unroll
    for (int d = 16; d; d >>= 1) val += __shfl_xor_sync(~0u, val, d);
    __shared__ float s[32];
    if ((tid & 31) == 0) s[tid >> 5] = val;
    __syncthreads();
    if (tid < 16) {
        float r = s[2 * tid] + s[2 * tid + 1];
        if (tid < nb) g_rterm[tid] = r;
    }
}

// ---------------------------------------------------------------------------
// Final: out[v] = tanh( relu(h[v]) . Wa[:64] + rterm[v/n] )
// ---------------------------------------------------------------------------
__global__ void final_kernel(const float* __restrict__ Hf,
                             const float* __restrict__ Wa,
                             float* __restrict__ out, int N,
                             const int* __restrict__ np)
{
    int n = *np;
    int v = (blockIdx.x * blockDim.x + threadIdx.x) >> 5;
    int lane = threadIdx.x & 31;
    if (v >= N) return;
    float2 hv = *(const float2*)&Hf[v * 64 + lane * 2];
    float2 wv = *(const float2*)&Wa[lane * 2];
    float val = fmaxf(hv.x, 0.f) * wv.x + fmaxf(hv.y, 0.f) * wv.y;
    #pragma unroll
    for (int d = 16; d; d >>= 1) val += __shfl_xor_sync(~0u, val, d);
    if (lane == 0) out[v] = tanhf(val + g_rterm[v / n]);
}

// ---------------------------------------------------------------------------
// Launch
// ---------------------------------------------------------------------------
extern "C" void kernel_launch(void* const* d_in, const int* in_sizes, int n_in,
                              void* d_out, int out_size)
{
    const float* x  = (const float*)d_in[0];
    const int*   ei = (const int*)  d_in[1];
    const float* W0 = (const float*)d_in[2];
    const float* b0 = (const float*)d_in[3];
    const float* Ws = (const float*)d_in[4];
    const float* bs = (const float*)d_in[5];
    const float* Wn = (const float*)d_in[6];
    const float* Wp = (const float*)d_in[7];
    const float* Wa = (const float*)d_in[8];
    const int*   np = (const int*)  d_in[9];
    float* out = (float*)d_out;

    const int N = in_sizes[0] / 128;   // 50000
    const int E = in_sizes[1] / 2;     // 800000

    void *pH, *pG;
    cudaGetSymbolAddress(&pH, g_H);
    cudaGetSymbolAddress(&pG, g_G);
    float* H = (float*)pH;
    float* G = (float*)pG;

    const int nb_scan = (N + 255) / 256;   // 196

    // --- CSR build ---
    zero_kernel<<<(N + 255) / 256, 256>>>(N);
    count_kernel<<<(E + 255) / 256, 256>>>(ei, E);
    scan_partial<<<nb_scan, 256>>>(N);
    scan_block<<<1, 256>>>(nb_scan);
    finalize_meta<<<(N + 255) / 256, 256>>>(N, E);
    fill_csr<<<(E + 255) / 256, 256>>>(ei, E);

    const int gemm_grid   = (N + 127) / 128;
    const int warp_grid   = (N * 32 + 255) / 256;

    // --- GCN layers ---
    gemm64<128, true><<<gemm_grid, 256>>>(x, W0, G, N);
    gather_relu<<<warp_grid, 256>>>(G, b0, H, N);
    for (int i = 0; i < 8; i++) {
        gemm64<64, true><<<gemm_grid, 256>>>(H, Ws + i * 64 * 64, G, N);
        gather_relu<<<warp_grid, 256>>>(G, bs + i * 64, H, N);
    }

    // --- node transform + pool + readout ---
    gemm64<64, false><<<gemm_grid, 256>>>(H, Wn, G, N);
    pool_kernel<<<256, 256>>>(G, N, np);
    graph_term<<<1, 1024>>>(Wp, Wa, N, np);
    final_kernel<<<warp_grid, 256>>>(G, Wa, out, N, np);
}

// round 3
// speedup vs baseline: 1.0043x; 1.0043x over previous
#include <cuda_runtime.h>
#include <cuda_bf16.h>
#include <math.h>

// ---------------------------------------------------------------------------
// Problem constants (fixed-shape registry problem)
//   N=50000 nodes, E=800000 edges, C_IN=128, C_H=64, 9 GCN layers
// ---------------------------------------------------------------------------
#define MAXN 50000
#define MAXE 800000
#define CH   64

// ---------------------------------------------------------------------------
// Scratch (device globals; no allocation allowed)
// ---------------------------------------------------------------------------
__device__ float g_H[MAXN * CH];        // current node features
__device__ float g_G[MAXN * CH];        // g = (h@W)[*dinv]  /  h@Wn at the end
__device__ int   g_cnt[MAXN];           // in-degree counts
__device__ int   g_rowptr[MAXN + 1];    // CSR row pointers (by dst)
__device__ int   g_cursor[MAXN];        // fill cursors
__device__ int   g_csr[MAXE];           // src ids sorted by dst
__device__ float g_dinv[MAXN];          // 1/sqrt(deg+1)
__device__ int   g_blocksum[256];       // scan partials
__device__ float g_pool[16 * CH];       // per-graph pooled features
__device__ float g_rterm[16];           // per-graph readout scalar

// ---------------------------------------------------------------------------
// f32x2 packed helpers (FFMA2: 2 MACs / issue slot)
// ---------------------------------------------------------------------------
__device__ __forceinline__ void fma2(unsigned long long& d,
                                     unsigned long long a,
                                     unsigned long long b) {
    asm("fma.rn.f32x2 %0, %1, %2, %0;" : "+l"(d) : "l"(a), "l"(b));
}
__device__ __forceinline__ unsigned long long packdup(float x) {
    unsigned long long r;
    asm("mov.b64 %0, {%1, %1};" : "=l"(r) : "f"(x));
    return r;
}

// ---------------------------------------------------------------------------
// Preprocessing: degree histogram + CSR build
// ---------------------------------------------------------------------------
__global__ void zero_kernel(int N) {
    int i = blockIdx.x * blockDim.x + threadIdx.x;
    if (i < N) g_cnt[i] = 0;
    if (i < 16 * CH) g_pool[i] = 0.f;
}

__global__ void count_kernel(const int* __restrict__ ei, int E) {
    int e = blockIdx.x * blockDim.x + threadIdx.x;
    if (e < E) atomicAdd(&g_cnt[ei[E + e]], 1);   // dst = ei[1][e]
}

__global__ void scan_partial(int N) {
    __shared__ int s[256];
    int t = threadIdx.x;
    int i = blockIdx.x * 256 + t;
    int v = (i < N) ? g_cnt[i] : 0;
    s[t] = v; __syncthreads();
    #pragma unroll
    for (int d = 1; d < 256; d <<= 1) {
        int x = (t >= d) ? s[t - d] : 0;
        __syncthreads();
        s[t] += x;
        __syncthreads();
    }
    if (i < N) g_rowptr[i] = s[t] - v;            // exclusive within block
    if (t == 255) g_blocksum[blockIdx.x] = s[255];
}

__global__ void scan_block(int nb) {
    __shared__ int s[256];
    int t = threadIdx.x;
    int v = (t < nb) ? g_blocksum[t] : 0;
    s[t] = v; __syncthreads();
    #pragma unroll
    for (int d = 1; d < 256; d <<= 1) {
        int x = (t >= d) ? s[t - d] : 0;
        __syncthreads();
        s[t] += x;
        __syncthreads();
    }
    if (t < nb) g_blocksum[t] = s[t] - v;         // exclusive
}

__global__ void finalize_meta(int N, int E) {
    int i = blockIdx.x * blockDim.x + threadIdx.x;
    if (i < N) {
        int rp = g_rowptr[i] + g_blocksum[i >> 8];
        g_rowptr[i] = rp;
        g_cursor[i] = rp;
        g_dinv[i]   = rsqrtf((float)g_cnt[i] + 1.0f);
        if (i == 0) g_rowptr[N] = E;
    }
}

__global__ void fill_csr(const int* __restrict__ ei, int E) {
    int e = blockIdx.x * blockDim.x + threadIdx.x;
    if (e < E) {
        int s = ei[e];
        int d = ei[E + e];
        int pos = atomicAdd(&g_cursor[d], 1);
        g_csr[pos] = s;
    }
}

// ---------------------------------------------------------------------------
// GEMM: Y[N,64] = (X[N,CIN] @ W[CIN,64]) * (dinv[r] if SCALE)  — fp32, FFMA2
// Block: 256 threads -> 128 rows x 64 cols; thread tile 8 rows x 4 cols as
// 16 packed b64 accumulators (row-pairs x 4 cols).
// ---------------------------------------------------------------------------
template <int CIN, bool SCALE>
__global__ void __launch_bounds__(256)
gemm64(const float* __restrict__ X, const float* __restrict__ W,
       float* __restrict__ Y, int N)
{
    __shared__ __align__(16) float hs[32][130];   // k-tile x row (even stride)
    __shared__ __align__(16) float ws[32][64];    // k-tile x col
    const int tid = threadIdx.x;
    const int tx  = tid & 15;        // col group (4 cols)
    const int ty  = tid >> 4;        // row group (8 rows)
    const int row0 = blockIdx.x * 128;

    unsigned long long acc[4][4];    // [row-pair][col], lo=even row, hi=odd
    #pragma unroll
    for (int p = 0; p < 4; p++)
        #pragma unroll
        for (int q = 0; q < 4; q++) acc[p][q] = 0ull;

    for (int k0 = 0; k0 < CIN; k0 += 32) {
        // stage X tile (transposed into smem, coalesced gmem reads)
        #pragma unroll
        for (int i = 0; i < 16; i++) {
            int idx = tid + 256 * i;          // 0..4095
            int r = idx >> 5, kk = idx & 31;
            int gr = row0 + r;
            hs[kk][r] = (gr < N) ? X[gr * CIN + k0 + kk] : 0.f;
        }
        // stage W tile
        #pragma unroll
        for (int i = 0; i < 8; i++) {
            int idx = tid + 256 * i;          // 0..2047
            int k = idx >> 6, c = idx & 63;
            ws[k][c] = W[(k0 + k) * 64 + c];
        }
        __syncthreads();
        #pragma unroll
        for (int k = 0; k < 32; k++) {
            unsigned long long hp[4];
            #pragma unroll
            for (int p = 0; p < 4; p++)
                hp[p] = *(const unsigned long long*)&hs[k][ty * 8 + p * 2];
            float4 wv = *(const float4*)&ws[k][tx * 4];
            unsigned long long wd[4];
            wd[0] = packdup(wv.x); wd[1] = packdup(wv.y);
            wd[2] = packdup(wv.z); wd[3] = packdup(wv.w);
            #pragma unroll
            for (int p = 0; p < 4; p++) {
                fma2(acc[p][0], hp[p], wd[0]);
                fma2(acc[p][1], hp[p], wd[1]);
                fma2(acc[p][2], hp[p], wd[2]);
                fma2(acc[p][3], hp[p], wd[3]);
            }
        }
        __syncthreads();
    }
    #pragma unroll
    for (int p = 0; p < 4; p++) {
        int r = row0 + ty * 8 + p * 2;
        if (r < N) {
            float s0 = SCALE ? g_dinv[r] : 1.0f;
            float s1 = SCALE ? g_dinv[r + 1] : 1.0f;
            float4 o0, o1;
            o0.x = __uint_as_float((unsigned)acc[p][0]) * s0;
            o1.x = __uint_as_float((unsigned)(acc[p][0] >> 32)) * s1;
            o0.y = __uint_as_float((unsigned)acc[p][1]) * s0;
            o1.y = __uint_as_float((unsigned)(acc[p][1] >> 32)) * s1;
            o0.z = __uint_as_float((unsigned)acc[p][2]) * s0;
            o1.z = __uint_as_float((unsigned)(acc[p][2] >> 32)) * s1;
            o0.w = __uint_as_float((unsigned)acc[p][3]) * s0;
            o1.w = __uint_as_float((unsigned)(acc[p][3] >> 32)) * s1;
            *(float4*)&Y[r * 64 + tx * 4] = o0;
            *(float4*)&Y[(r + 1) * 64 + tx * 4] = o1;
        }
    }
}

// ---------------------------------------------------------------------------
// Gather: H[v] = relu(dinv[v] * (sum over {v} u in(v)} s(u)*G[u]) + bias)
//   SRCSCALE=false: G rows already carry dinv (s(u)=1)
//   SRCSCALE=true : G rows unscaled, apply s(u)=dinv[u] per edge (layer 0,
//                   lets the GEMM run concurrently with the CSR build)
// warp per node; lane owns a float2 (2 channels)
// ---------------------------------------------------------------------------
template <bool SRCSCALE>
__global__ void gather_relu(const float* __restrict__ G,
                            const float* __restrict__ bias,
                            float* __restrict__ H, int N)
{
    int v = (blockIdx.x * blockDim.x + threadIdx.x) >> 5;
    int lane = threadIdx.x & 31;
    if (v >= N) return;

    int s = __ldg(&g_rowptr[v]), e = __ldg(&g_rowptr[v + 1]);
    float dv = g_dinv[v];

    float2 acc = *(const float2*)&G[v * 64 + lane * 2];  // self term
    if (SRCSCALE) { acc.x *= dv; acc.y *= dv; }

    for (int p = s; p < e; p += 32) {
        int m = min(32, e - p);
        int sl = (lane < m) ? __ldg(&g_csr[p + lane]) : 0;
        float dl = SRCSCALE ? ((lane < m) ? g_dinv[sl] : 0.f) : 0.f;
        for (int j = 0; j < m; j++) {
            int src = __shfl_sync(0xffffffffu, sl, j);
            float2 gv = *(const float2*)&G[src * 64 + lane * 2];
            if (SRCSCALE) {
                float ds = __shfl_sync(0xffffffffu, dl, j);
                acc.x = fmaf(gv.x, ds, acc.x);
                acc.y = fmaf(gv.y, ds, acc.y);
            } else {
                acc.x += gv.x; acc.y += gv.y;
            }
        }
    }
    float2 b2 = *(const float2*)&bias[lane * 2];
    float hx = fmaxf(fmaf(dv, acc.x, b2.x), 0.f);
    float hy = fmaxf(fmaf(dv, acc.y, b2.y), 0.f);
    *(float2*)&H[v * 64 + lane * 2] = make_float2(hx, hy);
}

// ---------------------------------------------------------------------------
// Global add pool: per-block smem accumulator (16 graphs x 64 ch), one
// global atomic flush per block.
// ---------------------------------------------------------------------------
__global__ void pool_kernel(const float* __restrict__ Hf, int N,
                            const int* __restrict__ np)
{
    __shared__ float sp[16 * CH];
    int n = *np;
    for (int i = threadIdx.x; i < 16 * CH; i += blockDim.x) sp[i] = 0.f;
    __syncthreads();

    long total = (long)N * 64;
    long stride = (long)gridDim.x * blockDim.x;
    int cur = -1; float accv = 0.f;
    for (long idx = blockIdx.x * (long)blockDim.x + threadIdx.x;
         idx < total; idx += stride) {
        int r = (int)(idx >> 6), c = (int)(idx & 63);
        int slot = (r / n) * 64 + c;
        if (slot != cur) {
            if (cur >= 0) atomicAdd(&sp[cur], accv);
            cur = slot; accv = 0.f;
        }
        accv += Hf[idx];
    }
    if (cur >= 0) atomicAdd(&sp[cur], accv);
    __syncthreads();
    for (int i = threadIdx.x; i < 16 * CH; i += blockDim.x)
        if (sp[i] != 0.f) atomicAdd(&g_pool[i], sp[i]);
}

// ---------------------------------------------------------------------------
// Per-graph readout scalar: rterm[b] = sum_c relu((pool@Wp)[b,c]) * Wa[64+c]
// ---------------------------------------------------------------------------
__global__ void graph_term(const float* __restrict__ Wp,
                           const float* __restrict__ Wa,
                           int N, const int* __restrict__ np)
{
    int n = *np; int nb = N / n; if (nb > 16) nb = 16;
    int tid = threadIdx.x;               // 1024 threads, 16 graphs x 64 ch
    int b = tid >> 6, c = tid & 63;
    float val = 0.f;
    if (b < nb) {
        float rep = 0.f;
        #pragma unroll 8
        for (int k = 0; k < 64; k++) rep += g_pool[b * 64 + k] * Wp[k * 64 + c];
        val = fmaxf(rep, 0.f) * Wa[64 + c];
    }
    #pragma unroll
    for (int d = 16; d; d >>= 1) val += __shfl_xor_sync(~0u, val, d);
    __shared__ float s[32];
    if ((tid & 31) == 0) s[tid >> 5] = val;
    __syncthreads();
    if (tid < 16) {
        float r = s[2 * tid] + s[2 * tid + 1];
        if (tid < nb) g_rterm[tid] = r;
    }
}

// ---------------------------------------------------------------------------
// Final: out[v] = tanh( relu(h[v]) . Wa[:64] + rterm[v/n] )
// ---------------------------------------------------------------------------
__global__ void final_kernel(const float* __restrict__ Hf,
                             const float* __restrict__ Wa,
                             float* __restrict__ out, int N,
                             const int* __restrict__ np)
{
    int n = *np;
    int v = (blockIdx.x * blockDim.x + threadIdx.x) >> 5;
    int lane = threadIdx.x & 31;
    if (v >= N) return;
    float2 hv = *(const float2*)&Hf[v * 64 + lane * 2];
    float2 wv = *(const float2*)&Wa[lane * 2];
    float val = fmaxf(hv.x, 0.f) * wv.x + fmaxf(hv.y, 0.f) * wv.y;
    #pragma unroll
    for (int d = 16; d; d >>= 1) val += __shfl_xor_sync(~0u, val, d);
    if (lane == 0) out[v] = tanhf(val + g_rterm[v / n]);
}

// ---------------------------------------------------------------------------
// Launch: CSR build forked to a side stream, overlapped with layer-0 GEMM
// ---------------------------------------------------------------------------
extern "C" void kernel_launch(void* const* d_in, const int* in_sizes, int n_in,
                              void* d_out, int out_size)
{
    const float* x  = (const float*)d_in[0];
    const int*   ei = (const int*)  d_in[1];
    const float* W0 = (const float*)d_in[2];
    const float* b0 = (const float*)d_in[3];
    const float* Ws = (const float*)d_in[4];
    const float* bs = (const float*)d_in[5];
    const float* Wn = (const float*)d_in[6];
    const float* Wp = (const float*)d_in[7];
    const float* Wa = (const float*)d_in[8];
    const int*   np = (const int*)  d_in[9];
    float* out = (float*)d_out;

    const int N = in_sizes[0] / 128;   // 50000
    const int E = in_sizes[1] / 2;     // 800000

    void *pH, *pG;
    cudaGetSymbolAddress(&pH, g_H);
    cudaGetSymbolAddress(&pG, g_G);
    float* H = (float*)pH;
    float* G = (float*)pG;

    const int nb_scan   = (N + 255) / 256;   // 196
    const int gemm_grid = (N + 127) / 128;
    const int warp_grid = (N * 32 + 255) / 256;

    // --- fork: CSR build on side stream, layer-0 GEMM on main stream ---
    cudaStream_t s2;
    cudaEvent_t evFork, evJoin;
    cudaStreamCreate(&s2);
    cudaEventCreateWithFlags(&evFork, cudaEventDisableTiming);
    cudaEventCreateWithFlags(&evJoin, cudaEventDisableTiming);

    cudaEventRecord(evFork, 0);
    cudaStreamWaitEvent(s2, evFork, 0);

    zero_kernel   <<<(N + 255) / 256, 256, 0, s2>>>(N);
    count_kernel  <<<(E + 255) / 256, 256, 0, s2>>>(ei, E);
    scan_partial  <<<nb_scan, 256, 0, s2>>>(N);
    scan_block    <<<1, 256, 0, s2>>>(nb_scan);
    finalize_meta <<<(N + 255) / 256, 256, 0, s2>>>(N, E);
    fill_csr      <<<(E + 255) / 256, 256, 0, s2>>>(ei, E);
    cudaEventRecord(evJoin, s2);

    // layer-0 GEMM (unscaled: no dependence on dinv/CSR)
    gemm64<128, false><<<gemm_grid, 256>>>(x, W0, G, N);

    cudaStreamWaitEvent(0, evJoin, 0);   // join before first gather

    // --- GCN layers ---
    gather_relu<true><<<warp_grid, 256>>>(G, b0, H, N);   // applies dinv[src]
    for (int i = 0; i < 8; i++) {
        gemm64<64, true><<<gemm_grid, 256>>>(H, Ws + i * 64 * 64, G, N);
        gather_relu<false><<<warp_grid, 256>>>(G, bs + i * 64, H, N);
    }

    // --- node transform + pool + readout ---
    gemm64<64, false><<<gemm_grid, 256>>>(H, Wn, G, N);
    pool_kernel<<<256, 256>>>(G, N, np);
    graph_term<<<1, 1024>>>(Wp, Wa, N, np);
    final_kernel<<<warp_grid, 256>>>(G, Wa, out, N, np);

    cudaStreamDestroy(s2);
    cudaEventDestroy(evFork);
    cudaEventDestroy(evJoin);
}